// round 4
// baseline (speedup 1.0000x reference)
#include <cuda_runtime.h>
#include <cstdint>

#define D 512
#define HW (D * D)            // 262144 = 2^18
#define NB 32                 // batch
#define IMG_ELEMS ((size_t)NB * 3 * HW)
#define LO 0.001f
#define HI 510.999f           // D - 1.001
#define NBLOCKS 8192          // (512/32)*(512/32)*32

__device__ float g_partials[NBLOCKS];
__device__ unsigned int g_ticket;   // zero-initialized; last block resets it

// One branch, one pixel. img points at batch-n's [3,HW] plane set.
// r stride 4 across channels (r[c*4]).
__device__ __forceinline__ void sample_branch(const float* __restrict__ img,
                                              float qx0, float qy0, float m,
                                              float* __restrict__ r,
                                              float& loss) {
    float qx = fminf(fmaxf(qx0, LO), HI);
    float qy = fminf(fmaxf(qy0, LO), HI);
    float dx = qx0 - qx;
    float dy = qy0 - qy;
    loss += dx * dx + dy * dy;

    float fx = floorf(qx);
    float fy = floorf(qy);
    float ax = qx - fx;              // in [0,1)
    float ay = qy - fy;

    int ifx = (int)fx, ify = (int)fy;
    int icx = ifx + (ax > 0.0f);     // == (int)ceilf(qx)
    int icy = ify + (ay > 0.0f);

    // weights: 1 - |q - nb|
    float wfx = 1.0f - ax;
    float wcx = 1.0f - ((float)icx - qx);
    float wfy = 1.0f - ay;
    float wcy = 1.0f - ((float)icy - qy);

    // ind = y + D * x
    int i00 = ify + (ifx << 9);
    int i10 = ify + (icx << 9);
    int i01 = icy + (ifx << 9);
    int i11 = icy + (icx << 9);

    float wff = wfx * wfy;
    float wcf = wcx * wfy;
    float wfc = wfx * wcy;
    float wcc = wcx * wcy;

#pragma unroll
    for (int c = 0; c < 3; c++) {
        const float* ic = img + (size_t)c * HW;
        float v = wff * __ldg(ic + i00)
                + wcf * __ldg(ic + i10)
                + wfc * __ldg(ic + i01)
                + wcc * __ldg(ic + i11);
        r[c * 4] += m * v;
    }
}

// Tile mapping: block = 32x32 pixel tile of one batch image.
//   lane (0..31)  -> y within tile (consecutive columns: 1 cache-line column)
//   warp (0..7)   -> 4 consecutive rows (x) via ILP
__global__ void __launch_bounds__(256) vm_main_kernel(
    const float* __restrict__ im1,
    const float* __restrict__ im2,
    const float* __restrict__ C,
    const float* __restrict__ M1,
    const float* __restrict__ M2,
    float* __restrict__ out,
    int write_loss) {

    int bid = blockIdx.x;
    int ty = (bid & 15) << 5;           // tile y origin
    int tx = ((bid >> 4) & 15) << 5;    // tile x origin
    int n  = bid >> 8;                  // batch

    int lane = threadIdx.x & 31;
    int w    = threadIdx.x >> 5;

    int y  = ty + lane;                 // column, fixed per thread
    int x0 = tx + (w << 2);             // first of 4 rows

    const float* Cn  = C  + (size_t)n * 2 * HW;
    const float* M1n = M1 + (size_t)n * HW;
    const float* M2n = M2 + (size_t)n * HW;
    const float* im1n = im1 + (size_t)n * 3 * HW;
    const float* im2n = im2 + (size_t)n * 3 * HW;

    float yf = (float)y;

    float r[12];
#pragma unroll
    for (int i = 0; i < 12; i++) r[i] = 0.0f;
    float loss = 0.0f;

#pragma unroll
    for (int i = 0; i < 4; i++) {
        int x = x0 + i;
        int p = (x << 9) + y;
        float xf = (float)x;

        float c0 = __ldg(Cn + p);        // row-flow
        float c1 = __ldg(Cn + p + HW);   // col-flow
        float m1 = __ldg(M1n + p);
        float m2 = __ldg(M2n + p);

        // branch a: im1 sampled at q + C, masked by M1
        sample_branch(im1n, xf + c0, yf + c1, m1, &r[i], loss);
        // branch b: im2 sampled at q - C, masked by M2
        sample_branch(im2n, xf - c0, yf - c1, m2, &r[i], loss);
    }

    // stores: per row i, per channel c — warp-coalesced 128B each
#pragma unroll
    for (int i = 0; i < 4; i++) {
        int p = ((x0 + i) << 9) + y;
#pragma unroll
        for (int c = 0; c < 3; c++) {
            out[(size_t)n * 3 * HW + (size_t)c * HW + p] = r[c * 4 + i];
        }
    }

    // ---- loss reduction: warp shfl -> smem -> per-block partial ----
#pragma unroll
    for (int off = 16; off > 0; off >>= 1)
        loss += __shfl_down_sync(0xFFFFFFFFu, loss, off);

    __shared__ float warp_part[8];
    __shared__ bool is_last;
    if (lane == 0) warp_part[w] = loss;
    __syncthreads();
    if (threadIdx.x == 0) {
        float v = warp_part[0];
#pragma unroll
        for (int k = 1; k < 8; k++) v += warp_part[k];
        g_partials[bid] = v;
        __threadfence();
        unsigned int t = atomicAdd(&g_ticket, 1u);
        is_last = (t == NBLOCKS - 1);
    }
    __syncthreads();

    // ---- last block: reduce all partials, write loss scalar, reset ticket ----
    if (is_last) {
        float s = 0.0f;
        for (int i = threadIdx.x; i < NBLOCKS; i += 256)
            s += g_partials[i];
#pragma unroll
        for (int off = 16; off > 0; off >>= 1)
            s += __shfl_down_sync(0xFFFFFFFFu, s, off);
        if (lane == 0) warp_part[w] = s;
        __syncthreads();
        if (threadIdx.x == 0) {
            float v = warp_part[0];
#pragma unroll
            for (int k = 1; k < 8; k++) v += warp_part[k];
            if (write_loss) {
                // la + lb = sum / (N*2*HW) / (D*D) * 0.01
                double denom = (double)NB * 2.0 * (double)HW;
                out[IMG_ELEMS] = (float)((double)v / denom * (0.01 / (double)(D * D)));
            }
            g_ticket = 0;   // reset for next (deterministic across calls)
        }
    }
}

extern "C" void kernel_launch(void* const* d_in, const int* in_sizes, int n_in,
                              void* d_out, int out_size) {
    const float* im1 = (const float*)d_in[0];
    const float* im2 = (const float*)d_in[1];
    const float* C   = (const float*)d_in[2];
    const float* M1  = (const float*)d_in[3];
    const float* M2  = (const float*)d_in[4];
    float* out = (float*)d_out;

    int write_loss = ((size_t)out_size > IMG_ELEMS) ? 1 : 0;
    vm_main_kernel<<<NBLOCKS, 256>>>(im1, im2, C, M1, M2, out, write_loss);
}

// round 5
// speedup vs baseline: 1.0113x; 1.0113x over previous
#include <cuda_runtime.h>
#include <cstdint>

#define D 512
#define HW (D * D)            // 262144 = 2^18
#define NB 32                 // batch
#define IMG_ELEMS ((size_t)NB * 3 * HW)
#define LO 0.001f
#define HI 510.999f           // D - 1.001
#define NBLOCKS 8192          // (512/32)*(512/32)*32

__device__ float g_partials[NBLOCKS];

// One branch, one pixel. img points at batch-n's [3,HW] plane set.
// r stride 4 across channels (r[c*4]).
__device__ __forceinline__ void sample_branch(const float* __restrict__ img,
                                              float qx0, float qy0, float m,
                                              float* __restrict__ r,
                                              float& loss) {
    float qx = fminf(fmaxf(qx0, LO), HI);
    float qy = fminf(fmaxf(qy0, LO), HI);
    float dx = qx0 - qx;
    float dy = qy0 - qy;
    loss += dx * dx + dy * dy;

    float fx = floorf(qx);
    float fy = floorf(qy);
    float ax = qx - fx;              // in [0,1)
    float ay = qy - fy;

    int ifx = (int)fx, ify = (int)fy;
    int icx = ifx + (ax > 0.0f);     // == (int)ceilf(qx)
    int icy = ify + (ay > 0.0f);

    // weights: 1 - |q - nb|
    float wfx = 1.0f - ax;
    float wcx = 1.0f - ((float)icx - qx);
    float wfy = 1.0f - ay;
    float wcy = 1.0f - ((float)icy - qy);

    // ind = y + D * x
    int i00 = ify + (ifx << 9);
    int i10 = ify + (icx << 9);
    int i01 = icy + (ifx << 9);
    int i11 = icy + (icx << 9);

    float wff = m * (wfx * wfy);
    float wcf = m * (wcx * wfy);
    float wfc = m * (wfx * wcy);
    float wcc = m * (wcx * wcy);

#pragma unroll
    for (int c = 0; c < 3; c++) {
        const float* ic = img + (size_t)c * HW;
        r[c * 4] += wff * __ldg(ic + i00)
                  + wcf * __ldg(ic + i10)
                  + wfc * __ldg(ic + i01)
                  + wcc * __ldg(ic + i11);
    }
}

// Tile mapping: block = 32x32 pixel tile of one batch image.
//   lane (0..31)  -> y within tile (consecutive columns: 1 cache-line column)
//   warp (0..7)   -> 4 consecutive rows (x) via ILP
__global__ void __launch_bounds__(256, 6) vm_main_kernel(
    const float* __restrict__ im1,
    const float* __restrict__ im2,
    const float* __restrict__ C,
    const float* __restrict__ M1,
    const float* __restrict__ M2,
    float* __restrict__ out) {

    int bid = blockIdx.x;
    int ty = (bid & 15) << 5;           // tile y origin
    int tx = ((bid >> 4) & 15) << 5;    // tile x origin
    int n  = bid >> 8;                  // batch

    int lane = threadIdx.x & 31;
    int w    = threadIdx.x >> 5;

    int y  = ty + lane;                 // column, fixed per thread
    int x0 = tx + (w << 2);             // first of 4 rows

    const float* Cn  = C  + (size_t)n * 2 * HW;
    const float* M1n = M1 + (size_t)n * HW;
    const float* M2n = M2 + (size_t)n * HW;
    const float* im1n = im1 + (size_t)n * 3 * HW;
    const float* im2n = im2 + (size_t)n * 3 * HW;

    float yf = (float)y;

    float r[12];
#pragma unroll
    for (int i = 0; i < 12; i++) r[i] = 0.0f;
    float loss = 0.0f;

#pragma unroll
    for (int i = 0; i < 4; i++) {
        int x = x0 + i;
        int p = (x << 9) + y;
        float xf = (float)x;

        float c0 = __ldg(Cn + p);        // row-flow
        float c1 = __ldg(Cn + p + HW);   // col-flow
        float m1 = __ldg(M1n + p);
        float m2 = __ldg(M2n + p);

        // branch a: im1 sampled at q + C, masked by M1
        sample_branch(im1n, xf + c0, yf + c1, m1, &r[i], loss);
        // branch b: im2 sampled at q - C, masked by M2
        sample_branch(im2n, xf - c0, yf - c1, m2, &r[i], loss);
    }

    // stores: per row i, per channel c — warp-coalesced 128B each
#pragma unroll
    for (int i = 0; i < 4; i++) {
        int p = ((x0 + i) << 9) + y;
#pragma unroll
        for (int c = 0; c < 3; c++) {
            out[(size_t)n * 3 * HW + (size_t)c * HW + p] = r[c * 4 + i];
        }
    }

    // ---- loss reduction: warp shfl -> smem -> per-block partial ----
#pragma unroll
    for (int off = 16; off > 0; off >>= 1)
        loss += __shfl_down_sync(0xFFFFFFFFu, loss, off);

    __shared__ float warp_part[8];
    if (lane == 0) warp_part[w] = loss;
    __syncthreads();
    if (threadIdx.x == 0) {
        float v = warp_part[0];
#pragma unroll
        for (int k = 1; k < 8; k++) v += warp_part[k];
        g_partials[bid] = v;
    }
}

__global__ void __launch_bounds__(256) vm_finalize_kernel(float* __restrict__ out) {
    int t = threadIdx.x;
    float s = 0.0f;
#pragma unroll 8
    for (int i = t; i < NBLOCKS; i += 256)
        s += g_partials[i];
#pragma unroll
    for (int off = 16; off > 0; off >>= 1)
        s += __shfl_down_sync(0xFFFFFFFFu, s, off);
    __shared__ float warp_part[8];
    int w = t >> 5, lane = t & 31;
    if (lane == 0) warp_part[w] = s;
    __syncthreads();
    if (t == 0) {
        float v = warp_part[0];
#pragma unroll
        for (int k = 1; k < 8; k++) v += warp_part[k];
        // la + lb = sum / (N*2*HW) / (D*D) * 0.01
        double denom = (double)NB * 2.0 * (double)HW;
        out[IMG_ELEMS] = (float)((double)v / denom * (0.01 / (double)(D * D)));
    }
}

extern "C" void kernel_launch(void* const* d_in, const int* in_sizes, int n_in,
                              void* d_out, int out_size) {
    const float* im1 = (const float*)d_in[0];
    const float* im2 = (const float*)d_in[1];
    const float* C   = (const float*)d_in[2];
    const float* M1  = (const float*)d_in[3];
    const float* M2  = (const float*)d_in[4];
    float* out = (float*)d_out;

    vm_main_kernel<<<NBLOCKS, 256>>>(im1, im2, C, M1, M2, out);

    if ((size_t)out_size > IMG_ELEMS) {
        vm_finalize_kernel<<<1, 256>>>(out);
    }
}

// round 6
// speedup vs baseline: 1.0930x; 1.0808x over previous
#include <cuda_runtime.h>
#include <cstdint>

#define D 512
#define HW (D * D)            // 262144 = 2^18
#define NB 32                 // batch
#define IMG_ELEMS ((size_t)NB * 3 * HW)
#define LO 0.001f
#define HI 510.999f           // D - 1.001
#define NBLOCKS 8192          // (512/32)*(512/32)*32

__device__ float g_partials[NBLOCKS];

// One branch, one pixel. img points at batch-n's [3,HW] plane set.
__device__ __forceinline__ void sample_branch(const float* __restrict__ img,
                                              float qx0, float qy0, float m,
                                              float r[3],
                                              float& loss) {
    float qx = fminf(fmaxf(qx0, LO), HI);
    float qy = fminf(fmaxf(qy0, LO), HI);
    float dx = qx0 - qx;
    float dy = qy0 - qy;
    loss += dx * dx + dy * dy;

    float fx = floorf(qx);
    float fy = floorf(qy);
    float ax = qx - fx;              // in [0,1)
    float ay = qy - fy;

    int ifx = (int)fx, ify = (int)fy;
    int icx = ifx + (ax > 0.0f);     // == (int)ceilf(qx)
    int icy = ify + (ay > 0.0f);

    // weights: 1 - |q - nb|
    float wfx = 1.0f - ax;
    float wcx = 1.0f - ((float)icx - qx);
    float wfy = 1.0f - ay;
    float wcy = 1.0f - ((float)icy - qy);

    // ind = y + D * x
    int i00 = ify + (ifx << 9);
    int i10 = ify + (icx << 9);
    int i01 = icy + (ifx << 9);
    int i11 = icy + (icx << 9);

    float wff = m * (wfx * wfy);
    float wcf = m * (wcx * wfy);
    float wfc = m * (wfx * wcy);
    float wcc = m * (wcx * wcy);

#pragma unroll
    for (int c = 0; c < 3; c++) {
        const float* ic = img + (size_t)c * HW;
        r[c] += wff * __ldg(ic + i00)
              + wcf * __ldg(ic + i10)
              + wfc * __ldg(ic + i01)
              + wcc * __ldg(ic + i11);
    }
}

// Tile mapping: block = 32x32 pixel tile of one batch image.
//   lane (0..31)  -> y within tile (consecutive columns: 1 cache-line column)
//   warp (0..7)   -> 4 consecutive rows (x) via ILP, stored per-row immediately
__global__ void __launch_bounds__(256, 6) vm_main_kernel(
    const float* __restrict__ im1,
    const float* __restrict__ im2,
    const float* __restrict__ C,
    const float* __restrict__ M1,
    const float* __restrict__ M2,
    float* __restrict__ out) {

    int bid = blockIdx.x;
    int ty = (bid & 15) << 5;           // tile y origin
    int tx = ((bid >> 4) & 15) << 5;    // tile x origin
    int n  = bid >> 8;                  // batch

    int lane = threadIdx.x & 31;
    int w    = threadIdx.x >> 5;

    int y  = ty + lane;                 // column, fixed per thread
    int x0 = tx + (w << 2);             // first of 4 rows

    const float* Cn  = C  + (size_t)n * 2 * HW;
    const float* M1n = M1 + (size_t)n * HW;
    const float* M2n = M2 + (size_t)n * HW;
    const float* im1n = im1 + (size_t)n * 3 * HW;
    const float* im2n = im2 + (size_t)n * 3 * HW;
    float* outn = out + (size_t)n * 3 * HW;

    float yf = (float)y;
    float loss = 0.0f;

#pragma unroll
    for (int i = 0; i < 4; i++) {
        int x = x0 + i;
        int p = (x << 9) + y;
        float xf = (float)x;

        float c0 = __ldg(Cn + p);        // row-flow
        float c1 = __ldg(Cn + p + HW);   // col-flow
        float m1 = __ldg(M1n + p);
        float m2 = __ldg(M2n + p);

        float r[3] = {0.0f, 0.0f, 0.0f};
        // branch a: im1 sampled at q + C, masked by M1
        sample_branch(im1n, xf + c0, yf + c1, m1, r, loss);
        // branch b: im2 sampled at q - C, masked by M2
        sample_branch(im2n, xf - c0, yf - c1, m2, r, loss);

        // store this row now: 3 warp-coalesced 128B stores
        outn[p]            = r[0];
        outn[p + HW]       = r[1];
        outn[p + 2 * HW]   = r[2];
    }

    // ---- loss reduction: warp shfl -> smem -> per-block partial ----
#pragma unroll
    for (int off = 16; off > 0; off >>= 1)
        loss += __shfl_down_sync(0xFFFFFFFFu, loss, off);

    __shared__ float warp_part[8];
    if (lane == 0) warp_part[w] = loss;
    __syncthreads();
    if (threadIdx.x == 0) {
        float v = warp_part[0];
#pragma unroll
        for (int k = 1; k < 8; k++) v += warp_part[k];
        g_partials[bid] = v;
    }
}

__global__ void __launch_bounds__(256) vm_finalize_kernel(float* __restrict__ out) {
    int t = threadIdx.x;
    float s = 0.0f;
#pragma unroll 8
    for (int i = t; i < NBLOCKS; i += 256)
        s += g_partials[i];
#pragma unroll
    for (int off = 16; off > 0; off >>= 1)
        s += __shfl_down_sync(0xFFFFFFFFu, s, off);
    __shared__ float warp_part[8];
    int w = t >> 5, lane = t & 31;
    if (lane == 0) warp_part[w] = s;
    __syncthreads();
    if (t == 0) {
        float v = warp_part[0];
#pragma unroll
        for (int k = 1; k < 8; k++) v += warp_part[k];
        // la + lb = sum / (N*2*HW) / (D*D) * 0.01
        double denom = (double)NB * 2.0 * (double)HW;
        out[IMG_ELEMS] = (float)((double)v / denom * (0.01 / (double)(D * D)));
    }
}

extern "C" void kernel_launch(void* const* d_in, const int* in_sizes, int n_in,
                              void* d_out, int out_size) {
    const float* im1 = (const float*)d_in[0];
    const float* im2 = (const float*)d_in[1];
    const float* C   = (const float*)d_in[2];
    const float* M1  = (const float*)d_in[3];
    const float* M2  = (const float*)d_in[4];
    float* out = (float*)d_out;

    vm_main_kernel<<<NBLOCKS, 256>>>(im1, im2, C, M1, M2, out);

    if ((size_t)out_size > IMG_ELEMS) {
        vm_finalize_kernel<<<1, 256>>>(out);
    }
}

// round 7
// speedup vs baseline: 1.1075x; 1.0133x over previous
#include <cuda_runtime.h>
#include <cstdint>

#define D 512
#define HW (D * D)            // 262144 = 2^18
#define NB 32                 // batch
#define IMG_ELEMS ((size_t)NB * 3 * HW)
#define LO 0.001f
#define HI 510.999f           // D - 1.001
#define NBLOCKS 16384         // 32 batch * 32 x-tiles(16 rows) * 16 y-tiles(32 cols)

__device__ __align__(16) float g_partials[NBLOCKS];

// One branch, one pixel. img points at batch-n's [3,HW] plane set.
__device__ __forceinline__ void sample_branch(const float* __restrict__ img,
                                              float qx0, float qy0, float m,
                                              float r[3],
                                              float& loss) {
    float qx = fminf(fmaxf(qx0, LO), HI);
    float qy = fminf(fmaxf(qy0, LO), HI);
    float dx = qx0 - qx;
    float dy = qy0 - qy;
    loss += dx * dx + dy * dy;

    float fx = floorf(qx);
    float fy = floorf(qy);
    float ax = qx - fx;              // in [0,1)
    float ay = qy - fy;

    int ifx = (int)fx, ify = (int)fy;
    int icx = ifx + (ax > 0.0f);     // == (int)ceilf(qx)
    int icy = ify + (ay > 0.0f);

    // weights: 1 - |q - nb|
    float wfx = 1.0f - ax;
    float wcx = 1.0f - ((float)icx - qx);
    float wfy = 1.0f - ay;
    float wcy = 1.0f - ((float)icy - qy);

    // ind = y + D * x
    int i00 = ify + (ifx << 9);
    int i10 = ify + (icx << 9);
    int i01 = icy + (ifx << 9);
    int i11 = icy + (icx << 9);

    float wff = m * (wfx * wfy);
    float wcf = m * (wcx * wfy);
    float wfc = m * (wfx * wcy);
    float wcc = m * (wcx * wcy);

#pragma unroll
    for (int c = 0; c < 3; c++) {
        const float* ic = img + (size_t)c * HW;
        r[c] += wff * __ldg(ic + i00)
              + wcf * __ldg(ic + i10)
              + wfc * __ldg(ic + i01)
              + wcc * __ldg(ic + i11);
    }
}

// Tile mapping: block = 16 rows (x) by 32 cols (y) of one batch image.
//   lane (0..31)  -> y within tile (1 cache-line column)
//   warp (0..7)   -> 2 consecutive rows (x) via ILP-2
__global__ void __launch_bounds__(256, 6) vm_main_kernel(
    const float* __restrict__ im1,
    const float* __restrict__ im2,
    const float* __restrict__ C,
    const float* __restrict__ M1,
    const float* __restrict__ M2,
    float* __restrict__ out) {

    int bid = blockIdx.x;
    int ty = (bid & 15) << 5;            // y-tile origin (16 tiles of 32)
    int tx = ((bid >> 4) & 31) << 4;     // x-tile origin (32 tiles of 16)
    int n  = bid >> 9;                   // batch

    int lane = threadIdx.x & 31;
    int w    = threadIdx.x >> 5;

    int y  = ty + lane;                  // column, fixed per thread
    int x0 = tx + (w << 1);              // first of 2 rows

    const float* Cn  = C  + (size_t)n * 2 * HW;
    const float* M1n = M1 + (size_t)n * HW;
    const float* M2n = M2 + (size_t)n * HW;
    const float* im1n = im1 + (size_t)n * 3 * HW;
    const float* im2n = im2 + (size_t)n * 3 * HW;
    float* outn = out + (size_t)n * 3 * HW;

    float yf = (float)y;
    float loss = 0.0f;

#pragma unroll
    for (int i = 0; i < 2; i++) {
        int x = x0 + i;
        int p = (x << 9) + y;
        float xf = (float)x;

        float c0 = __ldg(Cn + p);        // row-flow
        float c1 = __ldg(Cn + p + HW);   // col-flow
        float m1 = __ldg(M1n + p);
        float m2 = __ldg(M2n + p);

        float r[3] = {0.0f, 0.0f, 0.0f};
        // branch a: im1 sampled at q + C, masked by M1
        sample_branch(im1n, xf + c0, yf + c1, m1, r, loss);
        // branch b: im2 sampled at q - C, masked by M2
        sample_branch(im2n, xf - c0, yf - c1, m2, r, loss);

        outn[p]          = r[0];
        outn[p + HW]     = r[1];
        outn[p + 2 * HW] = r[2];
    }

    // ---- loss reduction: warp shfl -> smem -> per-block partial ----
#pragma unroll
    for (int off = 16; off > 0; off >>= 1)
        loss += __shfl_down_sync(0xFFFFFFFFu, loss, off);

    __shared__ float warp_part[8];
    if (lane == 0) warp_part[w] = loss;
    __syncthreads();
    if (threadIdx.x == 0) {
        float v = warp_part[0];
#pragma unroll
        for (int k = 1; k < 8; k++) v += warp_part[k];
        g_partials[bid] = v;
    }
}

__global__ void __launch_bounds__(1024) vm_finalize_kernel(float* __restrict__ out) {
    int t = threadIdx.x;
    const float4* p4 = (const float4*)g_partials;   // 4096 float4s
    float s = 0.0f;
#pragma unroll
    for (int i = 0; i < 4; i++) {
        float4 v = p4[t + i * 1024];
        s += (v.x + v.y) + (v.z + v.w);
    }
#pragma unroll
    for (int off = 16; off > 0; off >>= 1)
        s += __shfl_down_sync(0xFFFFFFFFu, s, off);
    __shared__ float warp_part[32];
    int w = t >> 5, lane = t & 31;
    if (lane == 0) warp_part[w] = s;
    __syncthreads();
    if (w == 0) {
        float v = warp_part[lane];
#pragma unroll
        for (int off = 16; off > 0; off >>= 1)
            v += __shfl_down_sync(0xFFFFFFFFu, v, off);
        if (lane == 0) {
            // la + lb = sum / (N*2*HW) / (D*D) * 0.01
            double denom = (double)NB * 2.0 * (double)HW;
            out[IMG_ELEMS] = (float)((double)v / denom * (0.01 / (double)(D * D)));
        }
    }
}

extern "C" void kernel_launch(void* const* d_in, const int* in_sizes, int n_in,
                              void* d_out, int out_size) {
    const float* im1 = (const float*)d_in[0];
    const float* im2 = (const float*)d_in[1];
    const float* C   = (const float*)d_in[2];
    const float* M1  = (const float*)d_in[3];
    const float* M2  = (const float*)d_in[4];
    float* out = (float*)d_out;

    vm_main_kernel<<<NBLOCKS, 256>>>(im1, im2, C, M1, M2, out);

    if ((size_t)out_size > IMG_ELEMS) {
        vm_finalize_kernel<<<1, 1024>>>(out);
    }
}